// round 16
// baseline (speedup 1.0000x reference)
#include <cuda_runtime.h>
#include <cstdint>

// Spiking MLP: s2 = ((x @ W1^T >= 1) @ W2^T >= 1)
// Hybrid GEMM1: CTA-typed kernel — FFMA2 CTAs saturate the fma pipe
// (fp32 f32x2, ~0.2 smem-B/MAC via broadcast) while LUT CTAs saturate the
// smem crossbar (s32 nibble-LUT, 1 B/MAC). Disjoint resources -> additive.
// GEMM2: pure FFMA2. All fp32 outputs exact per proven paths (rel_err 0.0).

static const int M_BATCH = 4096;
static const int IN_DIM  = 3136;   // 98 u32 words
static const int FEAT    = 6272;
static const int OUT_DIM = 500;

#define QSCALE  268435456.0f       /* 2^28 */
#define QTHRESH 268435456

// ---------------- device scratch ----------------
__device__ int32_t  g_w1t[3136ull * 6272ull];   // W1^T quantized [k][n] (LUT cols)
__device__ uint32_t g_xn [4096ull * 98ull];     // x bits
__device__ float    g_s1 [4096ull * 6272ull];   // hidden spikes f32

#define FMA2(d, a, b) \
    asm("fma.rn.f32x2 %0, %1, %2, %0;" : "+l"(d) : "l"(a), "l"(b))
__device__ __forceinline__ unsigned long long pack_dup(float x) {
    unsigned long long r;
    unsigned int u = __float_as_uint(x);
    asm("mov.b64 %0, {%1, %1};" : "=l"(r) : "r"(u));
    return r;
}

// ---------------- conversion kernels ----------------
__global__ void cvt_x_bits_kernel(const float* __restrict__ x, uint32_t* __restrict__ xn)
{
    int m    = blockIdx.x * 8 + (threadIdx.x >> 5);
    int lane = threadIdx.x & 31;
    const float* row = x + (size_t)m * 3136;
    for (int c = 0; c < 4; c++) {
        int lim = min(32, 98 - c * 32);
        uint32_t w = 0;
        for (int i = 0; i < lim; i++) {
            float v = row[(c * 32 + i) * 32 + lane];
            uint32_t b = __ballot_sync(0xFFFFFFFFu, v >= 0.5f);
            if (lane == i) w = b;
        }
        if (lane < lim) xn[(size_t)m * 98 + c * 32 + lane] = w;
    }
}

// W1 -> quantized transpose for LUT columns only (n >= base)
__global__ void cvt_w1t_kernel(const float* __restrict__ w, int32_t* __restrict__ wt, int base)
{
    int n = base + blockIdx.x * 256 + threadIdx.x;
    int k = blockIdx.y;
    if (n < 6272)
        wt[(size_t)k * 6272 + n] = __float2int_rn(w[(size_t)n * 3136 + k] * QSCALE);
}

// ---------------- hybrid GEMM ----------------
// blockIdx.x < nFF : FFMA2 tile, cols [bx*96, +96)
// else             : LUT tile,   cols [lutBase + (bx-nFF)*128, +128)
// M-tile 128 both. C = threshold(A @ B^T) f32.
#define HYB_SMEM (32768 + 512)

__global__ void __launch_bounds__(256, 2)
spike_hybrid_kernel(const float* __restrict__ A,    // [M,K] f32 (FF path)
                    const float* __restrict__ B,    // [N,K] f32 weights (FF path)
                    const int32_t* __restrict__ Wt, // [K][NLD] s32 (LUT path)
                    const uint32_t* __restrict__ An,// [M][AnStride] bits (LUT path)
                    int K, int Nreal, int NLD, int AnStride,
                    float* __restrict__ C, int ldC,
                    int nFF, int lutBase)
{
    extern __shared__ __align__(16) char smem[];
    const int tid = threadIdx.x;
    const int m0  = blockIdx.y * 128;

    if ((int)blockIdx.x < nFF) {
        // ================= FFMA2 path =================
        const int tx = tid & 15;          // 6 cols each
        const int ty = tid >> 4;          // 8 rows each
        const int n0 = blockIdx.x * 96;

        float* Asf = (float*)smem;              // [16][128] k-major
        float* Bsf = (float*)(smem + 8192);     // [96][17]  n-major padded

        const int am = tid >> 1, ah = (tid & 1) * 8;
        const float* Ap = A + (size_t)(m0 + am) * K + ah;
        const int bn = tid >> 1, bh = (tid & 1) * 8;
        const bool bstage = (tid < 192);
        const bool bok = bstage && (n0 + bn) < Nreal;
        const float* Bp = B + (size_t)(n0 + bn) * K + bh;

        unsigned long long acc[4][6];
#pragma unroll
        for (int p = 0; p < 4; p++)
#pragma unroll
            for (int j = 0; j < 6; j++) acc[p][j] = 0ull;

        const float4 z4 = make_float4(0.f, 0.f, 0.f, 0.f);
        float4 a0 = *(const float4*)(Ap);
        float4 a1 = *(const float4*)(Ap + 4);
        float4 b0 = bok ? *(const float4*)(Bp)     : z4;
        float4 b1 = bok ? *(const float4*)(Bp + 4) : z4;

        const int NIT = K >> 4;
        for (int it = 0; it < NIT; it++) {
            if (it > 0) __syncthreads();
            // stage
            Asf[(ah + 0) * 128 + am] = a0.x;
            Asf[(ah + 1) * 128 + am] = a0.y;
            Asf[(ah + 2) * 128 + am] = a0.z;
            Asf[(ah + 3) * 128 + am] = a0.w;
            Asf[(ah + 4) * 128 + am] = a1.x;
            Asf[(ah + 5) * 128 + am] = a1.y;
            Asf[(ah + 6) * 128 + am] = a1.z;
            Asf[(ah + 7) * 128 + am] = a1.w;
            if (bstage) {
                Bsf[bn * 17 + bh + 0] = b0.x;
                Bsf[bn * 17 + bh + 1] = b0.y;
                Bsf[bn * 17 + bh + 2] = b0.z;
                Bsf[bn * 17 + bh + 3] = b0.w;
                Bsf[bn * 17 + bh + 4] = b1.x;
                Bsf[bn * 17 + bh + 5] = b1.y;
                Bsf[bn * 17 + bh + 6] = b1.z;
                Bsf[bn * 17 + bh + 7] = b1.w;
            }
            __syncthreads();
            // prefetch next
            if (it + 1 < NIT) {
                const int kb = (it + 1) << 4;
                a0 = *(const float4*)(Ap + kb);
                a1 = *(const float4*)(Ap + kb + 4);
                b0 = bok ? *(const float4*)(Bp + kb)     : z4;
                b1 = bok ? *(const float4*)(Bp + kb + 4) : z4;
            }
            // compute 16 k-steps
#pragma unroll
            for (int kk = 0; kk < 16; kk++) {
                const float* ar = Asf + kk * 128 + ty * 8;
                unsigned long long ap0 = *(const unsigned long long*)(ar);
                unsigned long long ap1 = *(const unsigned long long*)(ar + 2);
                unsigned long long ap2 = *(const unsigned long long*)(ar + 4);
                unsigned long long ap3 = *(const unsigned long long*)(ar + 6);
                unsigned long long bd[6];
#pragma unroll
                for (int j = 0; j < 6; j++)
                    bd[j] = pack_dup(Bsf[(tx * 6 + j) * 17 + kk]);
#pragma unroll
                for (int j = 0; j < 6; j++) {
                    FMA2(acc[0][j], ap0, bd[j]);
                    FMA2(acc[1][j], ap1, bd[j]);
                    FMA2(acc[2][j], ap2, bd[j]);
                    FMA2(acc[3][j], ap3, bd[j]);
                }
            }
        }
        // epilogue
#pragma unroll
        for (int p = 0; p < 4; p++) {
            const int row = m0 + ty * 8 + 2 * p;
#pragma unroll
            for (int j = 0; j < 6; j++) {
                const int col = n0 + tx * 6 + j;
                if (col < Nreal) {
                    const unsigned long long v = acc[p][j];
                    const float lo = __uint_as_float((unsigned int)(v & 0xFFFFFFFFull));
                    const float hi = __uint_as_float((unsigned int)(v >> 32));
                    C[(size_t)row * ldC + col]       = (lo >= 1.0f) ? 1.0f : 0.0f;
                    C[(size_t)(row + 1) * ldC + col] = (hi >= 1.0f) ? 1.0f : 0.0f;
                }
            }
        }
    } else {
        // ================= LUT path (round-15 proven) =================
        int32_t  (*lut)[16][128] = (int32_t (*)[16][128])smem;   // 32 KB
        uint32_t* xs             = (uint32_t*)(smem + 32768);    // 128 words

        const int lane = tid & 31;
        const int wid  = tid >> 5;
        const int n0   = lutBase + ((int)blockIdx.x - nFF) * 128;

        const int NB = K >> 4;
        const int bcol = tid & 127;
        const int bp   = tid >> 7;

        int32_t acc[16][4];
#pragma unroll
        for (int m = 0; m < 16; m++)
#pragma unroll
            for (int j = 0; j < 4; j++) acc[m][j] = 0;

        int32_t wv[2][4];
#pragma unroll
        for (int h = 0; h < 2; h++)
#pragma unroll
            for (int j = 0; j < 4; j++)
                wv[h][j] = Wt[(size_t)((bp + 2 * h) * 4 + j) * NLD + n0 + bcol];

        const uint32_t lutb = (uint32_t)(lane * 16);

        for (int b = 0; b < NB; b++) {
#pragma unroll
            for (int h = 0; h < 2; h++) {
                const int p = bp + 2 * h;
                int32_t e1 = wv[h][0];
                int32_t e2 = wv[h][1];
                int32_t e3 = e2 + e1;
                int32_t e4 = wv[h][2];
                int32_t e5 = e4 + e1;
                int32_t e6 = e4 + e2;
                int32_t e7 = e4 + e3;
                int32_t e8 = wv[h][3];
                lut[p][0][bcol]  = 0;
                lut[p][1][bcol]  = e1;
                lut[p][2][bcol]  = e2;
                lut[p][3][bcol]  = e3;
                lut[p][4][bcol]  = e4;
                lut[p][5][bcol]  = e5;
                lut[p][6][bcol]  = e6;
                lut[p][7][bcol]  = e7;
                lut[p][8][bcol]  = e8;
                lut[p][9][bcol]  = e8 + e1;
                lut[p][10][bcol] = e8 + e2;
                lut[p][11][bcol] = e8 + e3;
                lut[p][12][bcol] = e8 + e4;
                lut[p][13][bcol] = e8 + e5;
                lut[p][14][bcol] = e8 + e6;
                lut[p][15][bcol] = e8 + e7;
            }
            if ((b & 1) == 0 && tid < 128)
                xs[tid] = An[(size_t)(m0 + tid) * AnStride + (b >> 1)];
            __syncthreads();

            if (b + 1 < NB) {
                const int kb = (b + 1) << 4;
#pragma unroll
                for (int h = 0; h < 2; h++)
#pragma unroll
                    for (int j = 0; j < 4; j++)
                        wv[h][j] = Wt[(size_t)(kb + (bp + 2 * h) * 4 + j) * NLD + n0 + bcol];
            }

            const uint32_t sh = (b & 1) * 16;
            const char* lbase = smem + lutb;
#pragma unroll
            for (int m = 0; m < 16; m++) {
                const uint32_t nv = xs[wid * 16 + m] >> sh;
                const int4 a = *(const int4*)(lbase +         (((nv      ) & 15) << 9));
                const int4 bq= *(const int4*)(lbase + 8192  + (((nv >>  4) & 15) << 9));
                const int4 c = *(const int4*)(lbase + 16384 + (((nv >>  8) & 15) << 9));
                const int4 d = *(const int4*)(lbase + 24576 + (((nv >> 12) & 15) << 9));
                acc[m][0] += (a.x + bq.x) + (c.x + d.x);
                acc[m][1] += (a.y + bq.y) + (c.y + d.y);
                acc[m][2] += (a.z + bq.z) + (c.z + d.z);
                acc[m][3] += (a.w + bq.w) + (c.w + d.w);
            }
            __syncthreads();
        }

        // f32 threshold epilogue
#pragma unroll
        for (int m = 0; m < 16; m++) {
            const int row = m0 + wid * 16 + m;
            float* dst = C + (size_t)row * ldC;
#pragma unroll
            for (int j = 0; j < 4; j++) {
                const int col = n0 + lane * 4 + j;
                if (col < Nreal)
                    dst[col] = (acc[m][j] >= QTHRESH) ? 1.0f : 0.0f;
            }
        }
    }
}

// ---------------- host launch ----------------
extern "C" void kernel_launch(void* const* d_in, const int* in_sizes, int n_in,
                              void* d_out, int out_size)
{
    const float* x  = (const float*)d_in[0];   // [4096, 3136]
    const float* W1 = (const float*)d_in[1];   // [6272, 3136]
    const float* W2 = (const float*)d_in[2];   // [500, 6272]
    float* out = (float*)d_out;                // [4096, 500]

    int32_t  *w1t;
    uint32_t *xn;
    float    *s1;
    cudaGetSymbolAddress((void**)&w1t, g_w1t);
    cudaGetSymbolAddress((void**)&xn,  g_xn);
    cudaGetSymbolAddress((void**)&s1,  g_s1);

    cudaFuncSetAttribute(spike_hybrid_kernel,
                         cudaFuncAttributeMaxDynamicSharedMemorySize, HYB_SMEM);

    const int NFF1    = 36;               // 36*96 = 3456 FFMA2 cols
    const int LUTBASE = 3456;             // 22*128 = 2816 LUT cols -> 6272 total

    // conversions
    cvt_x_bits_kernel<<<M_BATCH / 8, 256>>>(x, xn);
    cvt_w1t_kernel<<<dim3((FEAT - LUTBASE) / 256, IN_DIM), 256>>>(W1, w1t, LUTBASE);

    // GEMM1 (hybrid): s1 = spike(x @ W1^T)   M=4096, N=6272, K=3136
    {
        dim3 grid(NFF1 + 22, M_BATCH / 128);   // (58, 32)
        spike_hybrid_kernel<<<grid, 256, HYB_SMEM>>>(
            x, W1, w1t, xn, IN_DIM, FEAT, FEAT, 98,
            s1, FEAT, NFF1, LUTBASE);
    }
    // GEMM2 (pure FFMA2): out = spike(s1 @ W2^T)  M=4096, N=500, K=6272
    {
        dim3 grid(6, M_BATCH / 128);           // 6*96 = 576 >= 500
        spike_hybrid_kernel<<<grid, 256, HYB_SMEM>>>(
            s1, W2, nullptr, nullptr, FEAT, OUT_DIM, 0, 0,
            out, OUT_DIM, 6, 0);
    }
}

// round 17
// speedup vs baseline: 1.2592x; 1.2592x over previous
#include <cuda_runtime.h>
#include <cstdint>

// Spiking MLP: s2 = ((x @ W1^T >= 1) @ W2^T >= 1)
// Pure binary-activation LUT GEMM in s32 (proven rel_err 0.0 at 2^28 scale).
// Round-17: coalesced transpose-quantize converters, GEMM1 M-tile 256
// (halved build overhead), GEMM2 N-tile 64 (2 CTAs/SM, full chip coverage).

static const int M_BATCH = 4096;
static const int IN_DIM  = 3136;   // 98 u32 words
static const int FEAT    = 6272;   // 196 u32 words
static const int OUT_DIM = 500;
static const int OUT_PAD = 512;

#define QSCALE  268435456.0f       /* 2^28 (exact power-of-two scale) */
#define QTHRESH 268435456          /* 1.0 * 2^28 */

// ---------------- device scratch ----------------
__device__ int32_t  g_w1t[3136ull * 6272ull];   // W1^T quantized [k][n]
__device__ int32_t  g_w2t[6272ull * 512ull];    // W2^T quantized [k][n], padded
__device__ uint32_t g_xn [4096ull * 98ull];     // x bits
__device__ uint32_t g_s1n[4096ull * 196ull];    // hidden spike bits

// ---------------- conversion kernels ----------------
__global__ void cvt_x_bits_kernel(const float* __restrict__ x, uint32_t* __restrict__ xn)
{
    int m    = blockIdx.x * 8 + (threadIdx.x >> 5);
    int lane = threadIdx.x & 31;
    const float* row = x + (size_t)m * 3136;
    for (int c = 0; c < 4; c++) {
        int lim = min(32, 98 - c * 32);
        uint32_t w = 0;
        for (int i = 0; i < lim; i++) {
            float v = row[(c * 32 + i) * 32 + lane];
            uint32_t b = __ballot_sync(0xFFFFFFFFu, v >= 0.5f);
            if (lane == i) w = b;
        }
        if (lane < lim) xn[(size_t)m * 98 + c * 32 + lane] = w;
    }
}

// Coalesced transpose + quantize: in [R][Cin] f32 -> out [Cin][Rpad] s32,
// out[k][n] = rint(in[n][k] * 2^28), zero for n >= R. Block (32,8), 32x32 tiles.
__global__ void tq_kernel(const float* __restrict__ in, int32_t* __restrict__ out,
                          int R, int Cin, int Rpad)
{
    __shared__ float t[32][33];
    const int kb = blockIdx.x * 32;
    const int nb = blockIdx.y * 32;
    const int tx = threadIdx.x, ty = threadIdx.y;
#pragma unroll
    for (int i = 0; i < 4; i++) {
        const int n = nb + ty + i * 8;
        t[ty + i * 8][tx] = (n < R) ? in[(size_t)n * Cin + kb + tx] : 0.0f;
    }
    __syncthreads();
#pragma unroll
    for (int i = 0; i < 4; i++) {
        const int k = kb + ty + i * 8;
        out[(size_t)k * Rpad + nb + tx] = __float2int_rn(t[tx][ty + i * 8] * QSCALE);
    }
}

// ---------------- LUT GEMM ----------------
// C = threshold(Abits @ Wt_sum). Wt [K][NLD] s32 k-major; An [M][AnStride] bits.
// CTA: 2*MT threads. Tile M=MT (warp: 16 m), N=NT (lane: NT/32 cols).
// Build: 2*MT threads == 4*NT slices -> one 16-entry nibble-LUT slice each.
// Consume: per m, 4 vector LDS (16B or 8B) -> 1 B/MAC on the crossbar.
template <int MT, int NT>
__global__ void __launch_bounds__(2 * MT, (MT == 128) ? 2 : 1)
spike_lut_kernel(const int32_t* __restrict__ Wt,
                 const uint32_t* __restrict__ An,
                 int K, int NLD, int Nreal,
                 uint32_t* __restrict__ outBits, int outBitsStride,
                 float* __restrict__ outF,
                 int AnStride)
{
    constexpr int CL = NT / 32;                   // cols per lane (4 or 2)
    extern __shared__ __align__(16) char smem[];
    int32_t*  L  = (int32_t*)smem;                // [4][16][NT]
    uint32_t* xs = (uint32_t*)(smem + 4 * 16 * NT * 4);   // MT words

    const int tid  = threadIdx.x;
    const int lane = tid & 31;
    const int wid  = tid >> 5;
    const int n0   = blockIdx.x * NT;
    const int m0   = blockIdx.y * MT;

    const int NB = K >> 4;
    const int bp   = tid / NT;                    // nibble group 0..3
    const int bcol = tid % NT;

    int32_t acc[16][CL];
#pragma unroll
    for (int m = 0; m < 16; m++)
#pragma unroll
        for (int j = 0; j < CL; j++) acc[m][j] = 0;

    int32_t wv[4];
#pragma unroll
    for (int j = 0; j < 4; j++)
        wv[j] = Wt[(size_t)(bp * 4 + j) * NLD + n0 + bcol];

    const uint32_t lutb = (uint32_t)(lane * (CL * 4));

    for (int b = 0; b < NB; b++) {
        // ---- build one 16-entry slice (11 adds, coalesced STS) ----
        {
            int32_t* Ls = L + bp * 16 * NT + bcol;
            const int32_t e1 = wv[0];
            const int32_t e2 = wv[1];
            const int32_t e3 = e2 + e1;
            const int32_t e4 = wv[2];
            const int32_t e5 = e4 + e1;
            const int32_t e6 = e4 + e2;
            const int32_t e7 = e4 + e3;
            const int32_t e8 = wv[3];
            Ls[0 * NT]  = 0;
            Ls[1 * NT]  = e1;
            Ls[2 * NT]  = e2;
            Ls[3 * NT]  = e3;
            Ls[4 * NT]  = e4;
            Ls[5 * NT]  = e5;
            Ls[6 * NT]  = e6;
            Ls[7 * NT]  = e7;
            Ls[8 * NT]  = e8;
            Ls[9 * NT]  = e8 + e1;
            Ls[10 * NT] = e8 + e2;
            Ls[11 * NT] = e8 + e3;
            Ls[12 * NT] = e8 + e4;
            Ls[13 * NT] = e8 + e5;
            Ls[14 * NT] = e8 + e6;
            Ls[15 * NT] = e8 + e7;
        }
        if ((b & 1) == 0 && tid < MT)
            xs[tid] = An[(size_t)(m0 + tid) * AnStride + (b >> 1)];
        __syncthreads();

        // prefetch W for next batch (gmem latency hidden by consume)
        if (b + 1 < NB) {
            const int kb2 = (b + 1) << 4;
#pragma unroll
            for (int j = 0; j < 4; j++)
                wv[j] = Wt[(size_t)(kb2 + bp * 4 + j) * NLD + n0 + bcol];
        }

        // ---- consume: 16 m rows, 4 vector LDS each (conflict-free) ----
        const uint32_t sh = (b & 1) * 16;
        const char* lb = smem + lutb;
#pragma unroll
        for (int m = 0; m < 16; m++) {
            const uint32_t nv = xs[wid * 16 + m] >> sh;  // LDS broadcast
            if (CL == 4) {
                const int4 a = *(const int4*)(lb +             (((nv      ) & 15) * (NT * 4)));
                const int4 q = *(const int4*)(lb + 16*NT*4   + (((nv >>  4) & 15) * (NT * 4)));
                const int4 c = *(const int4*)(lb + 32*NT*4   + (((nv >>  8) & 15) * (NT * 4)));
                const int4 d = *(const int4*)(lb + 48*NT*4   + (((nv >> 12) & 15) * (NT * 4)));
                acc[m][0] += (a.x + q.x) + (c.x + d.x);
                acc[m][1] += (a.y + q.y) + (c.y + d.y);
                acc[m][2 % CL] += (a.z + q.z) + (c.z + d.z);
                acc[m][3 % CL] += (a.w + q.w) + (c.w + d.w);
            } else {
                const int2 a = *(const int2*)(lb +             (((nv      ) & 15) * (NT * 4)));
                const int2 q = *(const int2*)(lb + 16*NT*4   + (((nv >>  4) & 15) * (NT * 4)));
                const int2 c = *(const int2*)(lb + 32*NT*4   + (((nv >>  8) & 15) * (NT * 4)));
                const int2 d = *(const int2*)(lb + 48*NT*4   + (((nv >> 12) & 15) * (NT * 4)));
                acc[m][0] += (a.x + q.x) + (c.x + d.x);
                acc[m][1 % CL] += (a.y + q.y) + (c.y + d.y);
            }
        }
        __syncthreads();
    }

    // ---- threshold epilogue ----
    if (outBits) {
        if (CL == 4) {
            // lane owns cols n0+lane*4..+3 -> nibble; butterfly-OR packs 8 lanes/word
#pragma unroll
            for (int m = 0; m < 16; m++) {
                uint32_t nib = 0;
#pragma unroll
                for (int j = 0; j < 4; j++)
                    nib |= (acc[m][j % CL] >= QTHRESH ? 1u : 0u) << j;
                uint32_t v = nib << ((lane & 7) * 4);
                v |= __shfl_xor_sync(0xFFFFFFFFu, v, 1);
                v |= __shfl_xor_sync(0xFFFFFFFFu, v, 2);
                v |= __shfl_xor_sync(0xFFFFFFFFu, v, 4);
                if ((lane & 7) == 0) {
                    const int row = m0 + wid * 16 + m;
                    outBits[(size_t)row * outBitsStride + (n0 >> 5) + (lane >> 3)] = v;
                }
            }
        }
    } else {
#pragma unroll
        for (int m = 0; m < 16; m++) {
            const int row = m0 + wid * 16 + m;
            float* dst = outF + (size_t)row * Nreal;
#pragma unroll
            for (int j = 0; j < CL; j++) {
                const int col = n0 + lane * CL + j;
                if (col < Nreal)
                    dst[col] = (acc[m][j] >= QTHRESH) ? 1.0f : 0.0f;
            }
        }
    }
}

#define SMEM1 (32768 + 1024)    // MT=256, NT=128
#define SMEM2 (16384 + 512)     // MT=128, NT=64

// ---------------- host launch ----------------
extern "C" void kernel_launch(void* const* d_in, const int* in_sizes, int n_in,
                              void* d_out, int out_size)
{
    const float* x  = (const float*)d_in[0];   // [4096, 3136]
    const float* W1 = (const float*)d_in[1];   // [6272, 3136]
    const float* W2 = (const float*)d_in[2];   // [500, 6272]
    float* out = (float*)d_out;                // [4096, 500]

    int32_t  *w1t, *w2t;
    uint32_t *xn, *s1n;
    cudaGetSymbolAddress((void**)&w1t, g_w1t);
    cudaGetSymbolAddress((void**)&w2t, g_w2t);
    cudaGetSymbolAddress((void**)&xn,  g_xn);
    cudaGetSymbolAddress((void**)&s1n, g_s1n);

    cudaFuncSetAttribute((const void*)spike_lut_kernel<256, 128>,
                         cudaFuncAttributeMaxDynamicSharedMemorySize, SMEM1);
    cudaFuncSetAttribute((const void*)spike_lut_kernel<128, 64>,
                         cudaFuncAttributeMaxDynamicSharedMemorySize, SMEM2);

    // conversions (coalesced; deterministic every call)
    cvt_x_bits_kernel<<<M_BATCH / 8, 256>>>(x, xn);
    tq_kernel<<<dim3(IN_DIM / 32, FEAT / 32), dim3(32, 8)>>>(W1, w1t, FEAT, IN_DIM, FEAT);
    tq_kernel<<<dim3(FEAT / 32, OUT_PAD / 32), dim3(32, 8)>>>(W2, w2t, OUT_DIM, FEAT, OUT_PAD);

    // GEMM1: s1 bits = spike(x @ W1^T)   M=4096, N=6272, K=3136
    {
        dim3 grid(FEAT / 128, M_BATCH / 256);   // (49, 16)
        spike_lut_kernel<256, 128><<<grid, 512, SMEM1>>>(
            w1t, xn, IN_DIM, FEAT, FEAT, s1n, 196, nullptr, 98);
    }
    // GEMM2: out = spike(s1 @ W2^T)      M=4096, Npad=512, K=6272
    {
        dim3 grid(OUT_PAD / 64, M_BATCH / 128);  // (8, 32)
        spike_lut_kernel<128, 64><<<grid, 256, SMEM2>>>(
            w2t, s1n, FEAT, OUT_PAD, OUT_DIM, nullptr, 0, out, 196);
    }
}